// round 1
// baseline (speedup 1.0000x reference)
#include <cuda_runtime.h>

// NCELoss: N=4096 examples, E=1024 embed, K=50 noise samples (+1 target).
// Inputs (metadata order):
//   d_in[0] input  f32 [N,E]
//   d_in[1] target i32 [N]
//   d_in[2] noise_samples i32 [N,K]
//   d_in[3] noise  f32 [V]
//   d_in[4] weight f32 [V,E]
//   d_in[5] bias   f32 [V]
// Output: scalar f32 loss.

#define EDIM 1024
#define KNOISE 50
#define NORM_TERM 9.0f
#define NWARPS 8

__device__ double g_acc;

__global__ void zero_acc_kernel() { g_acc = 0.0; }

__global__ __launch_bounds__(NWARPS * 32) void nce_loss_kernel(
    const float* __restrict__ input,
    const int*   __restrict__ target,
    const int*   __restrict__ noise_samples,
    const float* __restrict__ noise,
    const float* __restrict__ weight,
    const float* __restrict__ bias)
{
    __shared__ float4 s_in[EDIM / 4];      // 4 KB: this example's input row
    __shared__ float  s_wsum[NWARPS];

    const int n    = blockIdx.x;
    const int tid  = threadIdx.x;
    const int lane = tid & 31;
    const int wid  = tid >> 5;

    // Stage input row into smem (vectorized, coalesced).
    const float4* in4 = reinterpret_cast<const float4*>(input + (size_t)n * EDIM);
    for (int i = tid; i < EDIM / 4; i += NWARPS * 32) s_in[i] = in4[i];
    __syncthreads();

    // Each warp handles columns j = wid, wid+8, ... over [0, K+1).
    // j==0 is the target column; j>=1 are noise columns.
    float acc = 0.0f;
    for (int j = wid; j < KNOISE + 1; j += NWARPS) {
        const int idx = (j == 0) ? __ldg(&target[n])
                                 : __ldg(&noise_samples[n * KNOISE + (j - 1)]);
        const float4* w4 = reinterpret_cast<const float4*>(weight + (size_t)idx * EDIM);

        // 1024-float dot: 8 x float4 per lane, front-batched for MLP.
        float s = 0.0f;
        #pragma unroll
        for (int i = 0; i < 8; i++) {
            const float4 w = __ldg(&w4[lane + 32 * i]);
            const float4 x = s_in[lane + 32 * i];
            s += w.x * x.x + w.y * x.y + w.z * x.z + w.w * x.w;
        }
        #pragma unroll
        for (int o = 16; o; o >>= 1) s += __shfl_xor_sync(0xffffffffu, s, o);

        if (lane == 0) {
            const float logit = s + __ldg(&bias[idx]);
            const float p  = expf(logit - NORM_TERM);
            const float kp = (float)KNOISE * __ldg(&noise[idx]);
            // j==0: rnn_loss = log(p / (p + k*pn_target))
            // j>=1: noise term = log(k*pn / (p + k*pn))
            const float num  = (j == 0) ? p : kp;
            acc += logf(num / (p + kp));
        }
    }

    if (lane == 0) s_wsum[wid] = acc;
    __syncthreads();

    if (wid == 0) {
        float v = (lane < NWARPS) ? s_wsum[lane] : 0.0f;
        #pragma unroll
        for (int o = NWARPS / 2; o; o >>= 1) v += __shfl_xor_sync(0xffffffffu, v, o);
        if (lane == 0) atomicAdd(&g_acc, (double)v);
    }
}

__global__ void finalize_kernel(float* out, int n) {
    out[0] = (float)(-g_acc / (double)n);
}

extern "C" void kernel_launch(void* const* d_in, const int* in_sizes, int n_in,
                              void* d_out, int out_size) {
    const float* input         = (const float*)d_in[0];
    const int*   target        = (const int*)  d_in[1];
    const int*   noise_samples = (const int*)  d_in[2];
    const float* noise         = (const float*)d_in[3];
    const float* weight        = (const float*)d_in[4];
    const float* bias          = (const float*)d_in[5];
    float* out = (float*)d_out;

    const int N = in_sizes[1];  // target element count

    zero_acc_kernel<<<1, 1>>>();
    nce_loss_kernel<<<N, NWARPS * 32>>>(input, target, noise_samples, noise, weight, bias);
    finalize_kernel<<<1, 1>>>(out, N);
}